// round 1
// baseline (speedup 1.0000x reference)
#include <cuda_runtime.h>
#include <math.h>

#define NN 8192

// One CTA per output row. 256 threads * 8 float4 = 8192 floats = one full row of w.
__global__ void __launch_bounds__(256, 8) izh_fused_kernel(
    const float* __restrict__ x_in,
    const float* __restrict__ v,
    const float* __restrict__ u,
    const float* __restrict__ g,
    const float* __restrict__ w,
    const float* __restrict__ a_p,
    const float* __restrict__ b_p,
    const float* __restrict__ c_p,
    const float* __restrict__ d_p,
    float* __restrict__ out)
{
    const int row = blockIdx.x;
    const float4* __restrict__ wrow = reinterpret_cast<const float4*>(w + (size_t)row * NN);
    const float4* __restrict__ g4   = reinterpret_cast<const float4*>(g);

    float sum = 0.0f;
    #pragma unroll
    for (int i = 0; i < 8; ++i) {
        const int idx = threadIdx.x + i * 256;
        const float4 a = wrow[idx];
        const float4 b = g4[idx];
        sum += a.x * b.x;
        sum += a.y * b.y;
        sum += a.z * b.z;
        sum += a.w * b.w;
    }

    // intra-warp reduction
    #pragma unroll
    for (int off = 16; off > 0; off >>= 1)
        sum += __shfl_xor_sync(0xffffffffu, sum, off);

    __shared__ float ssum[8];
    const int wid = threadIdx.x >> 5;
    if ((threadIdx.x & 31) == 0) ssum[wid] = sum;
    __syncthreads();

    if (threadIdx.x == 0) {
        float dot = 0.0f;
        #pragma unroll
        for (int i = 0; i < 8; ++i) dot += ssum[i];

        const float I  = dot + x_in[row];
        const float vv = v[row];
        const float uu = u[row];
        const float gg = g[row];

        // Izhikevich quadratic dynamics
        const float v1 = vv + (0.04f * vv * vv + 5.0f * vv + 140.0f - uu + I);

        // differentiable spike surrogate: sigmoid(4 * (v1 - 30))
        const float s = 1.0f / (1.0f + expf(-4.0f * (v1 - 30.0f)));

        // hard spike mask for state resets
        const float spk = (v1 >= 30.0f) ? 1.0f : 0.0f;
        const float ns  = 1.0f - spk;

        const float du = fabsf(a_p[row]) * (fabsf(b_p[row]) * v1 - uu);
        const float dg = -gg / 6.5f;

        out[row]           = ns * v1 + spk * c_p[row];          // v_out
        out[NN + row]      = s;                                  // spiked_s
        out[2 * NN + row]  = ns * (uu + du) + spk * d_p[row];    // u_out
        out[3 * NN + row]  = ns * (gg + dg) + spk;               // g_out
    }
}

extern "C" void kernel_launch(void* const* d_in, const int* in_sizes, int n_in,
                              void* d_out, int out_size)
{
    const float* x_in = (const float*)d_in[0];
    const float* v    = (const float*)d_in[1];
    const float* u    = (const float*)d_in[2];
    const float* g    = (const float*)d_in[3];
    const float* w    = (const float*)d_in[4];
    const float* a_p  = (const float*)d_in[5];
    const float* b_p  = (const float*)d_in[6];
    const float* c_p  = (const float*)d_in[7];
    const float* d_p  = (const float*)d_in[8];
    float* out = (float*)d_out;

    izh_fused_kernel<<<NN, 256>>>(x_in, v, u, g, w, a_p, b_p, c_p, d_p, out);
}

// round 2
// speedup vs baseline: 1.1456x; 1.1456x over previous
#include <cuda_runtime.h>
#include <math.h>

#define NN 8192

// One CTA per output row. 256 threads * 8 float4 = 8192 floats = one full row of w.
// w streamed with evict-first (__ldcs); g via read-only path (L1 resident across
// CTAs on the same SM within the launch); epilogue scalars prefetched up front.
__global__ void __launch_bounds__(256, 8) izh_fused_kernel(
    const float* __restrict__ x_in,
    const float* __restrict__ v,
    const float* __restrict__ u,
    const float* __restrict__ g,
    const float* __restrict__ w,
    const float* __restrict__ a_p,
    const float* __restrict__ b_p,
    const float* __restrict__ c_p,
    const float* __restrict__ d_p,
    float* __restrict__ out)
{
    const int row = blockIdx.x;
    const float4* __restrict__ wrow = reinterpret_cast<const float4*>(w + (size_t)row * NN);
    const float4* __restrict__ g4   = reinterpret_cast<const float4*>(g);

    // Prefetch epilogue scalars early (thread 0 only) so their DRAM latency
    // overlaps the w-row streaming instead of serializing after the reduction.
    float pre_x = 0.f, pre_v = 0.f, pre_u = 0.f, pre_g = 0.f;
    float pre_a = 0.f, pre_b = 0.f, pre_c = 0.f, pre_d = 0.f;
    if (threadIdx.x == 0) {
        pre_x = __ldg(&x_in[row]);
        pre_v = __ldg(&v[row]);
        pre_u = __ldg(&u[row]);
        pre_g = __ldg(&g[row]);
        pre_a = __ldg(&a_p[row]);
        pre_b = __ldg(&b_p[row]);
        pre_c = __ldg(&c_p[row]);
        pre_d = __ldg(&d_p[row]);
    }

    float sum = 0.0f;
    #pragma unroll
    for (int i = 0; i < 8; ++i) {
        const int idx = threadIdx.x + i * 256;
        const float4 a = __ldcs(&wrow[idx]);   // streaming: evict-first in L2
        const float4 b = __ldg(&g4[idx]);      // reused: keep in L1/L2
        sum += a.x * b.x;
        sum += a.y * b.y;
        sum += a.z * b.z;
        sum += a.w * b.w;
    }

    // intra-warp reduction
    #pragma unroll
    for (int off = 16; off > 0; off >>= 1)
        sum += __shfl_xor_sync(0xffffffffu, sum, off);

    __shared__ float ssum[8];
    const int wid = threadIdx.x >> 5;
    if ((threadIdx.x & 31) == 0) ssum[wid] = sum;
    __syncthreads();

    if (threadIdx.x == 0) {
        float dot = 0.0f;
        #pragma unroll
        for (int i = 0; i < 8; ++i) dot += ssum[i];

        const float I  = dot + pre_x;
        const float vv = pre_v;
        const float uu = pre_u;
        const float gg = pre_g;

        // Izhikevich quadratic dynamics
        const float v1 = vv + (0.04f * vv * vv + 5.0f * vv + 140.0f - uu + I);

        // differentiable spike surrogate: sigmoid(4 * (v1 - 30))
        const float s = 1.0f / (1.0f + expf(-4.0f * (v1 - 30.0f)));

        // hard spike mask for state resets
        const float spk = (v1 >= 30.0f) ? 1.0f : 0.0f;
        const float ns  = 1.0f - spk;

        const float du = fabsf(pre_a) * (fabsf(pre_b) * v1 - uu);
        const float dg = -gg / 6.5f;

        out[row]           = ns * v1 + spk * pre_c;           // v_out
        out[NN + row]      = s;                                // spiked_s
        out[2 * NN + row]  = ns * (uu + du) + spk * pre_d;     // u_out
        out[3 * NN + row]  = ns * (gg + dg) + spk;             // g_out
    }
}

extern "C" void kernel_launch(void* const* d_in, const int* in_sizes, int n_in,
                              void* d_out, int out_size)
{
    const float* x_in = (const float*)d_in[0];
    const float* v    = (const float*)d_in[1];
    const float* u    = (const float*)d_in[2];
    const float* g    = (const float*)d_in[3];
    const float* w    = (const float*)d_in[4];
    const float* a_p  = (const float*)d_in[5];
    const float* b_p  = (const float*)d_in[6];
    const float* c_p  = (const float*)d_in[7];
    const float* d_p  = (const float*)d_in[8];
    float* out = (float*)d_out;

    izh_fused_kernel<<<NN, 256>>>(x_in, v, u, g, w, a_p, b_p, c_p, d_p, out);
}

// round 3
// speedup vs baseline: 1.1532x; 1.0066x over previous
#include <cuda_runtime.h>
#include <math.h>

#define NN 8192

// Two rows per CTA, 256 threads. Each thread: 8 iters x (2 w-float4 + 1 g-float4),
// i.e. 16 outstanding streaming loads per thread for w, with g amortized over
// both rows. w evict-first (__ldcs), g read-only (L1-resident within launch).
__global__ void __launch_bounds__(256) izh_fused_kernel(
    const float* __restrict__ x_in,
    const float* __restrict__ v,
    const float* __restrict__ u,
    const float* __restrict__ g,
    const float* __restrict__ w,
    const float* __restrict__ a_p,
    const float* __restrict__ b_p,
    const float* __restrict__ c_p,
    const float* __restrict__ d_p,
    float* __restrict__ out)
{
    const int row0 = blockIdx.x * 2;
    const float4* __restrict__ w0 = reinterpret_cast<const float4*>(w + (size_t)row0 * NN);
    const float4* __restrict__ w1 = reinterpret_cast<const float4*>(w + (size_t)(row0 + 1) * NN);
    const float4* __restrict__ g4 = reinterpret_cast<const float4*>(g);

    // Threads 0 and 1 prefetch the epilogue scalars for row0/row1 so their
    // DRAM latency overlaps the w streaming.
    float pre_x = 0.f, pre_v = 0.f, pre_u = 0.f, pre_g = 0.f;
    float pre_a = 0.f, pre_b = 0.f, pre_c = 0.f, pre_d = 0.f;
    if (threadIdx.x < 2) {
        const int r = row0 + threadIdx.x;
        pre_x = __ldg(&x_in[r]);
        pre_v = __ldg(&v[r]);
        pre_u = __ldg(&u[r]);
        pre_g = __ldg(&g[r]);
        pre_a = __ldg(&a_p[r]);
        pre_b = __ldg(&b_p[r]);
        pre_c = __ldg(&c_p[r]);
        pre_d = __ldg(&d_p[r]);
    }

    float s0 = 0.0f, s1 = 0.0f;
    #pragma unroll
    for (int i = 0; i < 8; ++i) {
        const int idx = threadIdx.x + i * 256;
        const float4 a0 = __ldcs(&w0[idx]);
        const float4 a1 = __ldcs(&w1[idx]);
        const float4 b  = __ldg(&g4[idx]);
        s0 += a0.x * b.x; s0 += a0.y * b.y; s0 += a0.z * b.z; s0 += a0.w * b.w;
        s1 += a1.x * b.x; s1 += a1.y * b.y; s1 += a1.z * b.z; s1 += a1.w * b.w;
    }

    // intra-warp reductions (both rows)
    #pragma unroll
    for (int off = 16; off > 0; off >>= 1) {
        s0 += __shfl_xor_sync(0xffffffffu, s0, off);
        s1 += __shfl_xor_sync(0xffffffffu, s1, off);
    }

    __shared__ float ssum[2][8];
    const int wid = threadIdx.x >> 5;
    if ((threadIdx.x & 31) == 0) {
        ssum[0][wid] = s0;
        ssum[1][wid] = s1;
    }
    __syncthreads();

    if (threadIdx.x < 2) {
        const int r = row0 + threadIdx.x;
        float dot = 0.0f;
        #pragma unroll
        for (int i = 0; i < 8; ++i) dot += ssum[threadIdx.x][i];

        const float I  = dot + pre_x;
        const float vv = pre_v;
        const float uu = pre_u;
        const float gg = pre_g;

        // Izhikevich quadratic dynamics
        const float v1 = vv + (0.04f * vv * vv + 5.0f * vv + 140.0f - uu + I);

        // differentiable spike surrogate: sigmoid(4 * (v1 - 30))
        const float s = 1.0f / (1.0f + expf(-4.0f * (v1 - 30.0f)));

        // hard spike mask for state resets
        const float spk = (v1 >= 30.0f) ? 1.0f : 0.0f;
        const float ns  = 1.0f - spk;

        const float du = fabsf(pre_a) * (fabsf(pre_b) * v1 - uu);
        const float dg = -gg / 6.5f;

        out[r]           = ns * v1 + spk * pre_c;           // v_out
        out[NN + r]      = s;                                // spiked_s
        out[2 * NN + r]  = ns * (uu + du) + spk * pre_d;     // u_out
        out[3 * NN + r]  = ns * (gg + dg) + spk;             // g_out
    }
}

extern "C" void kernel_launch(void* const* d_in, const int* in_sizes, int n_in,
                              void* d_out, int out_size)
{
    const float* x_in = (const float*)d_in[0];
    const float* v    = (const float*)d_in[1];
    const float* u    = (const float*)d_in[2];
    const float* g    = (const float*)d_in[3];
    const float* w    = (const float*)d_in[4];
    const float* a_p  = (const float*)d_in[5];
    const float* b_p  = (const float*)d_in[6];
    const float* c_p  = (const float*)d_in[7];
    const float* d_p  = (const float*)d_in[8];
    float* out = (float*)d_out;

    izh_fused_kernel<<<NN / 2, 256>>>(x_in, v, u, g, w, a_p, b_p, c_p, d_p, out);
}